// round 1
// baseline (speedup 1.0000x reference)
#include <cuda_runtime.h>

#define BATCH 8
#define TPTS 30000
#define NPTS (BATCH*TPTS)          // 240000
#define H 128
#define H2 256
#define R2 4096
#define PTILE 128
#define NTILES (NPTS/PTILE)        // 1875
#define NTHREADS 256
#define KC 8
#define PSTRIDE 129
#define OUTN (3*BATCH*H*R2)        // 12582912
#define PLANEN (3*BATCH*R2*H)      // 12582912
#define CNTN (3*BATCH*R2)          // 98304

typedef unsigned long long u64;

// ---- scratch (device globals; no runtime allocation allowed) ----
__device__ float g_net[(size_t)NPTS * H];      // ~123 MB
__device__ float g_plane[(size_t)PLANEN];      // ~50 MB
__device__ float g_cnt[CNTN];

// ---- packed f32x2 helpers (Blackwell FFMA2 path) ----
__device__ __forceinline__ u64 pack2(float x) {
    u64 r; asm("mov.b64 %0, {%1, %1};" : "=l"(r) : "f"(x)); return r;
}
__device__ __forceinline__ u64 pack2v(float lo, float hi) {
    u64 r; asm("mov.b64 %0, {%1, %2};" : "=l"(r) : "f"(lo), "f"(hi)); return r;
}
__device__ __forceinline__ void ffma2(u64 &d, u64 a, u64 b) {
    asm("fma.rn.f32x2 %0, %1, %2, %0;" : "+l"(d) : "l"(a), "l"(b));
}
__device__ __forceinline__ void unpack2(u64 v, float &lo, float &hi) {
    asm("mov.b64 {%0, %1}, %2;" : "=f"(lo), "=f"(hi) : "l"(v));
}

__device__ __forceinline__ void atomicMaxF(float* addr, float v) {
    if (v >= 0.0f) atomicMax((int*)addr, __float_as_int(v));
    else           atomicMin((unsigned int*)addr, __float_as_uint(v));
}

// ---- weight chunk loader: 8 rows x 128 cols, one float4 per thread ----
__device__ __forceinline__ void load_wchunk(float* dst, const float* __restrict__ W,
                                            int chunk, int tid) {
    int r  = tid >> 5;
    int c4 = (tid & 31) << 2;
    float4 v = *(const float4*)(W + (size_t)(chunk * KC + r) * H + c4);
    *(float4*)(dst + r * H + c4) = v;
}

// ---- one GEMM stage: acc[8][4] (f32x2 pairs) += relu?(A[k][p]) * W[k][c] ----
// Thread (ty,tx): points ty*8..+7, cols {tx*4..+3, 64+tx*4..+3}.
template<bool RELUA>
__device__ __forceinline__ void gemm_stage(const float* A, int kdim,
                                           const float* __restrict__ W,
                                           float* wb, u64 acc[8][4],
                                           int ty, int tx, int tid) {
    int nch = kdim / KC;
    load_wchunk(wb, W, 0, tid);
    __syncthreads();
    for (int ch = 0; ch < nch; ch++) {
        const float* cur = wb + (ch & 1) * (KC * H);
        if (ch + 1 < nch) load_wchunk(wb + ((ch + 1) & 1) * (KC * H), W, ch + 1, tid);
#pragma unroll
        for (int kk = 0; kk < KC; kk++) {
            const float* arow = A + (ch * KC + kk) * PSTRIDE + ty * 8;
            u64 a2[8];
#pragma unroll
            for (int i = 0; i < 8; i++) {
                float a = arow[i];
                if (RELUA) a = fmaxf(a, 0.0f);
                a2[i] = pack2(a);
            }
            const float* brow = cur + kk * H + tx * 4;
            float4 bv0 = *(const float4*)(brow);
            float4 bv1 = *(const float4*)(brow + 64);
            u64 b0 = pack2v(bv0.x, bv0.y), b1 = pack2v(bv0.z, bv0.w);
            u64 b2 = pack2v(bv1.x, bv1.y), b3 = pack2v(bv1.z, bv1.w);
#pragma unroll
            for (int i = 0; i < 8; i++) {
                ffma2(acc[i][0], a2[i], b0);
                ffma2(acc[i][1], a2[i], b1);
                ffma2(acc[i][2], a2[i], b2);
                ffma2(acc[i][3], a2[i], b3);
            }
        }
        __syncthreads();
    }
}

// ---- fused resnet block (mode 0: fc_pos input; mode 1: concat(net, pooled)) ----
__global__ void __launch_bounds__(NTHREADS, 1)
resnet_kernel(int mode,
              const float* __restrict__ pts,
              const int* __restrict__ ixz, const int* __restrict__ ixy,
              const int* __restrict__ iyz,
              const float* __restrict__ fcpw, const float* __restrict__ fcpb,
              const float* __restrict__ w0, const float* __restrict__ b0,
              const float* __restrict__ w1, const float* __restrict__ b1,
              const float* __restrict__ wsc) {
    extern __shared__ float sm[];
    float* xs = sm;                      // [H2][PSTRIDE]  input x (transposed)
    float* ns = xs + H2 * PSTRIDE;       // [H][PSTRIDE]   relu(net1) (transposed)
    float* wb = ns + H * PSTRIDE;        // [2][KC][H]     weight double buffer

    int tid = threadIdx.x;
    int pbase = blockIdx.x * PTILE;

    // ---- fill xs[k][p] ----
    if (mode == 0) {
        float wk0 = fcpw[tid], wk1 = fcpw[H2 + tid], wk2 = fcpw[2 * H2 + tid];
        float bk = fcpb[tid];
        for (int s = 0; s < PTILE; s++) {
            int gp = pbase + s;
            float p0 = pts[gp * 3 + 0], p1 = pts[gp * 3 + 1], p2 = pts[gp * 3 + 2];
            xs[tid * PSTRIDE + s] = bk + p0 * wk0 + p1 * wk1 + p2 * wk2;
        }
    } else {
        if (tid < H) {
            for (int s = 0; s < PTILE; s++) {
                int gp = pbase + s;
                xs[tid * PSTRIDE + s] = g_net[(size_t)gp * H + tid];
            }
        } else {
            int ch = tid - H;
            for (int s = 0; s < PTILE; s++) {
                int gp = pbase + s;
                int b = gp / TPTS;
                int i0 = ixz[gp], i1 = ixy[gp], i2 = iyz[gp];
                float v = g_plane[(size_t)((0 * BATCH + b) * R2 + i0) * H + ch]
                        + g_plane[(size_t)((1 * BATCH + b) * R2 + i1) * H + ch]
                        + g_plane[(size_t)((2 * BATCH + b) * R2 + i2) * H + ch];
                xs[(H + ch) * PSTRIDE + s] = v;
            }
        }
    }

    int tx = tid & 15, ty = tid >> 4;
    int cb0 = tx * 4, cb1 = 64 + tx * 4;

    u64 acc[8][4];
#pragma unroll
    for (int i = 0; i < 8; i++)
#pragma unroll
        for (int j = 0; j < 4; j++) acc[i][j] = 0ULL;

    // stage 1: net1 = relu(x) @ w0 + b0  (relu stored into ns)
    gemm_stage<true>(xs, H2, w0, wb, acc, ty, tx, tid);
    {
        float bb[8];
#pragma unroll
        for (int jj = 0; jj < 4; jj++) { bb[jj] = b0[cb0 + jj]; bb[4 + jj] = b0[cb1 + jj]; }
#pragma unroll
        for (int i = 0; i < 8; i++) {
            int p = ty * 8 + i;
            float lo, hi;
            unpack2(acc[i][0], lo, hi);
            ns[(cb0 + 0) * PSTRIDE + p] = fmaxf(lo + bb[0], 0.f);
            ns[(cb0 + 1) * PSTRIDE + p] = fmaxf(hi + bb[1], 0.f);
            unpack2(acc[i][1], lo, hi);
            ns[(cb0 + 2) * PSTRIDE + p] = fmaxf(lo + bb[2], 0.f);
            ns[(cb0 + 3) * PSTRIDE + p] = fmaxf(hi + bb[3], 0.f);
            unpack2(acc[i][2], lo, hi);
            ns[(cb1 + 0) * PSTRIDE + p] = fmaxf(lo + bb[4], 0.f);
            ns[(cb1 + 1) * PSTRIDE + p] = fmaxf(hi + bb[5], 0.f);
            unpack2(acc[i][3], lo, hi);
            ns[(cb1 + 2) * PSTRIDE + p] = fmaxf(lo + bb[6], 0.f);
            ns[(cb1 + 3) * PSTRIDE + p] = fmaxf(hi + bb[7], 0.f);
        }
    }

    // stage 2+3: acc = relu(net1) @ w1 ; acc += x @ wsc ; out = acc + b1
#pragma unroll
    for (int i = 0; i < 8; i++)
#pragma unroll
        for (int j = 0; j < 4; j++) acc[i][j] = 0ULL;

    gemm_stage<false>(ns, H, w1, wb, acc, ty, tx, tid);
    gemm_stage<false>(xs, H2, wsc, wb, acc, ty, tx, tid);

    {
        float bb[8];
#pragma unroll
        for (int jj = 0; jj < 4; jj++) { bb[jj] = b1[cb0 + jj]; bb[4 + jj] = b1[cb1 + jj]; }
#pragma unroll
        for (int i = 0; i < 8; i++) {
            int p = ty * 8 + i;
            int gp = pbase + p;
            float v[8];
            unpack2(acc[i][0], v[0], v[1]);
            unpack2(acc[i][1], v[2], v[3]);
            unpack2(acc[i][2], v[4], v[5]);
            unpack2(acc[i][3], v[6], v[7]);
            float4 o0 = make_float4(v[0] + bb[0], v[1] + bb[1], v[2] + bb[2], v[3] + bb[3]);
            float4 o1 = make_float4(v[4] + bb[4], v[5] + bb[5], v[6] + bb[6], v[7] + bb[7]);
            *(float4*)(&g_net[(size_t)gp * H + cb0]) = o0;
            *(float4*)(&g_net[(size_t)gp * H + cb1]) = o1;
        }
    }
}

// ---- plane scratch init to -FLT_MAX bits ----
__global__ void init_plane_kernel() {
    int i = blockIdx.x * NTHREADS + threadIdx.x;   // over PLANEN/4
    uint4 v = make_uint4(0xFF7FFFFFu, 0xFF7FFFFFu, 0xFF7FFFFFu, 0xFF7FFFFFu);
    ((uint4*)g_plane)[i] = v;
}

// ---- scatter max of g_net into 3 planes ----
__global__ void scatter_max_kernel(const int* __restrict__ ixz,
                                   const int* __restrict__ ixy,
                                   const int* __restrict__ iyz) {
    int i = blockIdx.x * NTHREADS + threadIdx.x;   // over NPTS*H
    float v = g_net[i];
    int p = i >> 7;
    int ch = i & 127;
    int b = p / TPTS;
    atomicMaxF(&g_plane[(size_t)((0 * BATCH + b) * R2 + ixz[p]) * H + ch], v);
    atomicMaxF(&g_plane[(size_t)((1 * BATCH + b) * R2 + ixy[p]) * H + ch], v);
    atomicMaxF(&g_plane[(size_t)((2 * BATCH + b) * R2 + iyz[p]) * H + ch], v);
}

// ---- zero output + counts ----
__global__ void zero_kernel(float* __restrict__ out) {
    int i = blockIdx.x * NTHREADS + threadIdx.x;   // over OUTN/4
    ((float4*)out)[i] = make_float4(0.f, 0.f, 0.f, 0.f);
    if (i < CNTN / 4) ((float4*)g_cnt)[i] = make_float4(0.f, 0.f, 0.f, 0.f);
}

// ---- per-bin counts ----
__global__ void count_kernel(const int* __restrict__ ixz,
                             const int* __restrict__ ixy,
                             const int* __restrict__ iyz) {
    int p = blockIdx.x * NTHREADS + threadIdx.x;
    if (p >= NPTS) return;
    int b = p / TPTS;
    atomicAdd(&g_cnt[(0 * BATCH + b) * R2 + ixz[p]], 1.0f);
    atomicAdd(&g_cnt[(1 * BATCH + b) * R2 + ixy[p]], 1.0f);
    atomicAdd(&g_cnt[(2 * BATCH + b) * R2 + iyz[p]], 1.0f);
}

// ---- final: c = net @ fc_c + b, scatter-add into [3][B][CD][R2] ----
__global__ void __launch_bounds__(NTHREADS, 1)
final_kernel(const int* __restrict__ ixz, const int* __restrict__ ixy,
             const int* __restrict__ iyz,
             const float* __restrict__ wc, const float* __restrict__ bc,
             float* __restrict__ out) {
    extern __shared__ float sm[];
    float* xs = sm;                    // [H][PSTRIDE]
    float* wb = xs + H * PSTRIDE;      // [2][KC][H]
    int tid = threadIdx.x;
    int pbase = blockIdx.x * PTILE;

    for (int s = 0; s < PTILE; s += 2) {
        int p = s + (tid >> 7);
        int gp = pbase + p;
        int k = tid & 127;
        xs[k * PSTRIDE + p] = g_net[(size_t)gp * H + k];
    }

    int tx = tid & 15, ty = tid >> 4;
    int cb0 = tx * 4, cb1 = 64 + tx * 4;

    u64 acc[8][4];
#pragma unroll
    for (int i = 0; i < 8; i++)
#pragma unroll
        for (int j = 0; j < 4; j++) acc[i][j] = 0ULL;

    gemm_stage<false>(xs, H, wc, wb, acc, ty, tx, tid);

    float bb[8];
#pragma unroll
    for (int jj = 0; jj < 4; jj++) { bb[jj] = bc[cb0 + jj]; bb[4 + jj] = bc[cb1 + jj]; }

#pragma unroll
    for (int i = 0; i < 8; i++) {
        int p = ty * 8 + i;
        int gp = pbase + p;
        int b = gp / TPTS;
        int i0 = ixz[gp], i1 = ixy[gp], i2 = iyz[gp];
        float v[8];
        unpack2(acc[i][0], v[0], v[1]);
        unpack2(acc[i][1], v[2], v[3]);
        unpack2(acc[i][2], v[4], v[5]);
        unpack2(acc[i][3], v[6], v[7]);
#pragma unroll
        for (int jj = 0; jj < 8; jj++) {
            int c = (jj < 4) ? (cb0 + jj) : (cb1 + jj - 4);
            float val = v[jj] + bb[jj];
            atomicAdd(out + (((0 * BATCH + b) * H + c) << 12) + i0, val);
            atomicAdd(out + (((1 * BATCH + b) * H + c) << 12) + i1, val);
            atomicAdd(out + (((2 * BATCH + b) * H + c) << 12) + i2, val);
        }
    }
}

// ---- divide by counts ----
__global__ void div_kernel(float* __restrict__ out) {
    int i = blockIdx.x * NTHREADS + threadIdx.x;   // over OUTN
    float c = g_cnt[(i >> 19) * R2 + (i & 4095)];
    out[i] = out[i] / fmaxf(c, 1.0f);
}

extern "C" void kernel_launch(void* const* d_in, const int* in_sizes, int n_in,
                              void* d_out, int out_size) {
    const float* pts  = (const float*)d_in[0];
    const int*   ixz  = (const int*)d_in[1];
    const int*   ixy  = (const int*)d_in[2];
    const int*   iyz  = (const int*)d_in[3];
    const float* fcpw = (const float*)d_in[4];
    const float* fcpb = (const float*)d_in[5];
    const float* fc0w = (const float*)d_in[6];
    const float* fc0b = (const float*)d_in[7];
    const float* fc1w = (const float*)d_in[8];
    const float* fc1b = (const float*)d_in[9];
    const float* scw  = (const float*)d_in[10];
    const float* fccw = (const float*)d_in[11];
    const float* fccb = (const float*)d_in[12];
    float* out = (float*)d_out;

    const int RSMEM = (H2 * PSTRIDE + H * PSTRIDE + 2 * KC * H) * (int)sizeof(float); // 206336
    const int FSMEM = (H * PSTRIDE + 2 * KC * H) * (int)sizeof(float);                // 74240
    cudaFuncSetAttribute(resnet_kernel, cudaFuncAttributeMaxDynamicSharedMemorySize, RSMEM);
    cudaFuncSetAttribute(final_kernel,  cudaFuncAttributeMaxDynamicSharedMemorySize, FSMEM);

    // block 0 (fc_pos fused)
    resnet_kernel<<<NTILES, NTHREADS, RSMEM>>>(0, pts, ixz, ixy, iyz, fcpw, fcpb,
                                               fc0w, fc0b, fc1w, fc1b, scw);
    // blocks 1..4 with pooling
    for (int it = 1; it < 5; it++) {
        init_plane_kernel<<<PLANEN / 4 / NTHREADS, NTHREADS>>>();
        scatter_max_kernel<<<NPTS * H / NTHREADS, NTHREADS>>>(ixz, ixy, iyz);
        resnet_kernel<<<NTILES, NTHREADS, RSMEM>>>(1, pts, ixz, ixy, iyz, fcpw, fcpb,
                                                   fc0w + (size_t)it * H2 * H,
                                                   fc0b + (size_t)it * H,
                                                   fc1w + (size_t)it * H * H,
                                                   fc1b + (size_t)it * H,
                                                   scw  + (size_t)it * H2 * H);
    }
    // final projection + plane means
    zero_kernel<<<OUTN / 4 / NTHREADS, NTHREADS>>>(out);
    count_kernel<<<(NPTS + NTHREADS - 1) / NTHREADS, NTHREADS>>>(ixz, ixy, iyz);
    final_kernel<<<NTILES, NTHREADS, FSMEM>>>(ixz, ixy, iyz, fccw, fccb, out);
    div_kernel<<<OUTN / NTHREADS, NTHREADS>>>(out);
}